// round 15
// baseline (speedup 1.0000x reference)
#include <cuda_runtime.h>
#include <cuda_fp16.h>
#include <cstdint>

#define G     128
#define RSB   132              // padded row stride in BYTES (33 words)
#define GRSB  (G*RSB)          // 16896 bytes per slice
#define NL    200000
#define DX    3.125f
#define CC    0.99658f         // ICC*log2(e)*DX^2
#define KW2C  2.8952918f       // KW2/DX^2
#define TFRAC 0.2016f
#define EOFF  (-0.7016f)       // 0.5 - TFRAC - 1
#define THREADS 256
#define LPT   4
#define LPC   (THREADS*LPT)            // 1024
#define NCTA  ((NL + LPC - 1)/LPC)     // 196 per axis -> 588 CTAs -> 1 wave @ 4 CTA/SM
#define NSTAGE 3

#define SLICE_BYTES  GRSB
#define SMEM_BYTES   (128 + NSTAGE*SLICE_BYTES)   // 50816 -> 4 CTA/SM

// u8 slice-major padded volumes, one per axis
__device__ uint8_t g_tx[G*G*RSB];
__device__ uint8_t g_ty[G*G*RSB];
__device__ uint8_t g_tz[G*G*RSB];

__device__ __forceinline__ uint32_t quant4(float4 v) {
    int b0 = min((int)(v.x * 256.0f), 255);
    int b1 = min((int)(v.y * 256.0f), 255);
    int b2 = min((int)(v.z * 256.0f), 255);
    int b3 = min((int)(v.w * 256.0f), 255);
    return (uint32_t)b0 | ((uint32_t)b1 << 8) | ((uint32_t)b2 << 16) | ((uint32_t)b3 << 24);
}

// Vectorized fused transform (proven). block (32,8), grid (4, G).
__global__ void trans_all_kernel(const float* __restrict__ img) {
    __shared__ uint8_t tzt[G][33];     // [k][j_local], stride 33 -> conflict-free scatter
    const int i  = blockIdx.y;
    const int jb = blockIdx.x * 32;
    const int tx = threadIdx.x;        // k-word index (0..31)
    const int ty = threadIdx.y;
    const int tid = ty * 32 + tx;

    #pragma unroll
    for (int r = 0; r < 4; r++) {
        const int jl = ty + r * 8;
        const int j  = jb + jl;
        const float4 v = *(const float4*)(img + (size_t)(i*G + j)*G + 4*tx);
        const uint32_t w = quant4(v);
        *(uint32_t*)(g_tx + (size_t)(i*G + j)*RSB + 4*tx) = w;
        *(uint32_t*)(g_ty + (size_t)(j*G + i)*RSB + 4*tx) = w;
        tzt[4*tx + 0][jl] = (uint8_t)(w);
        tzt[4*tx + 1][jl] = (uint8_t)(w >> 8);
        tzt[4*tx + 2][jl] = (uint8_t)(w >> 16);
        tzt[4*tx + 3][jl] = (uint8_t)(w >> 24);
    }
    __syncthreads();
    #pragma unroll
    for (int it = 0; it < 4; it++) {
        const int idx = tid + it * 256;        // 1024 words total
        const int k  = idx >> 3;
        const int wj = idx & 7;
        uint32_t w = (uint32_t)tzt[k][4*wj]
                   | ((uint32_t)tzt[k][4*wj + 1] << 8)
                   | ((uint32_t)tzt[k][4*wj + 2] << 16)
                   | ((uint32_t)tzt[k][4*wj + 3] << 24);
        *(uint32_t*)(g_tz + (size_t)(k*G + i)*RSB + jb + 4*wj) = w;
    }
}

// ---------------- TMA / mbarrier helpers (proven) ----------------
__device__ __forceinline__ void mbar_init(uint32_t mbar, uint32_t count) {
    asm volatile("mbarrier.init.shared::cta.b64 [%0], %1;" :: "r"(mbar), "r"(count) : "memory");
}
__device__ __forceinline__ void mbar_expect_tx(uint32_t mbar, uint32_t bytes) {
    asm volatile("mbarrier.arrive.expect_tx.shared::cta.b64 _, [%0], %1;"
                 :: "r"(mbar), "r"(bytes) : "memory");
}
__device__ __forceinline__ void mbar_wait(uint32_t mbar, uint32_t phase) {
    asm volatile(
        "{\n\t"
        ".reg .pred P1;\n\t"
        "LAB_WAIT_%=:\n\t"
        "mbarrier.try_wait.parity.acquire.cta.shared::cta.b64 P1, [%0], %1, 0x989680;\n\t"
        "@P1 bra LAB_DONE_%=;\n\t"
        "bra.uni LAB_WAIT_%=;\n\t"
        "LAB_DONE_%=:\n\t"
        "}"
        :: "r"(mbar), "r"(phase) : "memory");
}
__device__ __forceinline__ void bulk_g2s(uint32_t dst, const void* src, uint32_t bytes, uint32_t mbar) {
    asm volatile("cp.async.bulk.shared::cluster.global.mbarrier::complete_tx::bytes [%0], [%1], %2, [%3];"
                 :: "r"(dst), "l"(src), "r"(bytes), "r"(mbar) : "memory");
}

__global__ __launch_bounds__(THREADS, 4)
void proj_kernel(const float* __restrict__ lx,
                 const float* __restrict__ ly,
                 const float* __restrict__ lz,
                 float* __restrict__ out)
{
    extern __shared__ __align__(128) unsigned char smem_raw[];
    const uint32_t smem_base = (uint32_t)__cvta_generic_to_shared(smem_raw);
    const uint32_t mbar0 = smem_base;            // 3 mbarriers, 8 B apart
    uint8_t* sbuf = (uint8_t*)(smem_raw + 128);

    const int axis = blockIdx.y;
    const int tid  = threadIdx.x;
    const int cta_base = blockIdx.x * LPC;

    const float* lors;
    const uint8_t* vol;
    int q0, q1;
    if (axis == 0)      { lors = lx; vol = g_tx; q0 = 1; q1 = 2; }
    else if (axis == 1) { lors = ly; vol = g_ty; q0 = 0; q1 = 2; }
    else                { lors = lz; vol = g_tz; q0 = 0; q1 = 1; }

    // per-LOR params in CELL units, prefolded by -(TFRAC+1).
    float ua0[LPT], va0[LPT], ddx[LPT], ddy[LPT], total[LPT];
    #pragma unroll
    for (int l = 0; l < LPT; l++) {
        int gi = cta_base + l*THREADS + tid;
        int lr = gi < NL ? gi : NL - 1;
        const float* L6 = lors + lr * 6;
        float px = L6[q0], py = L6[q1];
        ddx[l] = (L6[q0+3] - px) * (1.0f/400.0f);
        ddy[l] = (L6[q1+3] - py) * (1.0f/400.0f);
        ua0[l] = fmaf(px, 0.32f, 64.0f - (TFRAC + 1.0f)) + 0.5f * ddx[l];
        va0[l] = fmaf(py, 0.32f, 64.0f - (TFRAC + 1.0f)) + 0.5f * ddy[l];
        total[l] = 0.0f;
    }

    const __half2 nCC2   = __float2half2_rn(-CC);
    const __half2 KW2C2  = __float2half2_rn(KW2C);
    const __half2 zero2  = __float2half2_rn(0.0f);
    const __half2 B10235 = __float2half2_rn(1023.5f);
    const __half2 C01    = __halves2half2(__float2half(EOFF), __float2half(EOFF + 1.0f));
    const __half2 C22    = __float2half2_rn(2.0f);

    if (tid == 0) {
        #pragma unroll
        for (int s = 0; s < NSTAGE; s++) mbar_init(mbar0 + s*8, 1);
        asm volatile("fence.proxy.async.shared::cta;" ::: "memory");
    }
    __syncthreads();
    if (tid == 0) {
        #pragma unroll
        for (int s = 0; s < NSTAGE; s++) {
            mbar_expect_tx(mbar0 + s*8, SLICE_BYTES);
            bulk_g2s(smem_base + 128 + s*SLICE_BYTES, vol + (size_t)s*GRSB, SLICE_BYTES, mbar0 + s*8);
        }
    }

    int s = 0, pf = 0;
    float kf = 0.0f;
    for (int k = 0; k < G; k++) {
        mbar_wait(mbar0 + s*8, pf);
        const uint8_t* slice = sbuf + s * GRSB;

        #pragma unroll
        for (int l = 0; l < LPT; l++) {
            const float ua = fmaf(kf, ddx[l], ua0[l]);
            const float va = fmaf(kf, ddy[l], va0[l]);

            float af = floorf(ua);
            af = fminf(fmaxf(af, 0.0f), 124.0f);
            float cf = floorf(va);
            cf = fminf(fmaxf(cf, 0.0f), 124.0f);
            const int alo = (int)af;
            const int clo = (int)cf;
            const int d   = clo & 3;
            const int cW  = clo - d;
            const uint32_t selp = 0x3210u + (uint32_t)d * 0x1111u;

            const float eR = af - ua;      // EOFF folded into C01
            const float fR = cf - va;

            // col (f+m)^2 table, m=0..3, fully packed
            __half2 f2  = __hadd2(__float2half2_rn(fR), C01);   // (y0, y1)
            __half2 S0  = __hmul2(f2, f2);
            __half2 f2b = __hadd2(f2, C22);                     // (y2, y3)
            __half2 S1  = __hmul2(f2b, f2b);
            const __half2 P0 = h2exp2(__hmul2(S0, nCC2));
            const __half2 P1 = h2exp2(__hmul2(S1, nCC2));

            // row (e+a)^2 table, a=0..3, fully packed
            __half2 e2  = __hadd2(__float2half2_rn(eR), C01);   // (x0, x1)
            __half2 X01 = __hmul2(e2, e2);
            __half2 e2b = __hadd2(e2, C22);                     // (x2, x3)
            __half2 X23 = __hmul2(e2b, e2b);
            const __half2 W01 = h2exp2(__hmul2(X01, nCC2));
            const __half2 W23 = h2exp2(__hmul2(X23, nCC2));
            const __half2 L01 = __hsub2(KW2C2, X01);
            const __half2 L23 = __hsub2(KW2C2, X23);

            __half2 lb[4], wb[4];
            lb[0] = __low2half2(L01);  lb[1] = __high2half2(L01);
            lb[2] = __low2half2(L23);  lb[3] = __high2half2(L23);
            wb[0] = __low2half2(W01);  wb[1] = __high2half2(W01);
            wb[2] = __low2half2(W23);  wb[3] = __high2half2(W23);

            const uint8_t* rp = slice + alo * RSB + cW;
            __half2 acc2 = zero2;

            #pragma unroll
            for (int a = 0; a < 4; a++) {
                const uint32_t w0 = *(const uint32_t*)(rp);
                const uint32_t w1 = *(const uint32_t*)(rp + 4);
                const uint32_t p  = __byte_perm(w0, w1, selp);
                const uint32_t e0 = __byte_perm(p, 0x64646464u, 0x4140u);
                const uint32_t e1 = __byte_perm(p, 0x64646464u, 0x4342u);
                const __half2 V0 = __hsub2(*(const __half2*)&e0, B10235);
                const __half2 V1 = __hsub2(*(const __half2*)&e1, B10235);

                __half2 r2 = __hmul2(__hmul2(__hle2(S0, lb[a]), P0), V0);
                r2 = __hfma2(__hmul2(__hle2(S1, lb[a]), P1), V1, r2);
                acc2 = __hfma2(wb[a], r2, acc2);
                rp += RSB;
            }

            const float2 fr = __half22float2(acc2);
            total[l] += fr.x + fr.y;
        }

        __syncthreads();   // all warps of this CTA done with stage s
        if (tid == 0 && k + NSTAGE < G) {
            mbar_expect_tx(mbar0 + s*8, SLICE_BYTES);
            bulk_g2s(smem_base + 128 + s*SLICE_BYTES,
                     vol + (size_t)(k + NSTAGE)*GRSB, SLICE_BYTES, mbar0 + s*8);
        }
        s++; if (s == NSTAGE) { s = 0; pf ^= 1; }
        kf += 1.0f;
    }

    #pragma unroll
    for (int l = 0; l < LPT; l++) {
        int gi = cta_base + l*THREADS + tid;
        if (gi < NL) {
            // path = DX * sqrt(ddx^2 + ddy^2 + 1); u8 decode scale 1/256
            float sfac = sqrtf(fmaf(ddx[l], ddx[l], fmaf(ddy[l], ddy[l], 1.0f)));
            out[axis * NL + gi] = total[l] * (DX / 256.0f) * sfac;
        }
    }
}

extern "C" void kernel_launch(void* const* d_in, const int* in_sizes, int n_in,
                              void* d_out, int out_size)
{
    (void)in_sizes; (void)n_in; (void)out_size;
    const float* image = (const float*)d_in[0];
    const float* xl    = (const float*)d_in[1];
    const float* yl    = (const float*)d_in[2];
    const float* zl    = (const float*)d_in[3];
    float* out = (float*)d_out;

    static bool attr_set = false;
    if (!attr_set) {
        cudaFuncSetAttribute(proj_kernel, cudaFuncAttributeMaxDynamicSharedMemorySize, SMEM_BYTES);
        attr_set = true;
    }

    trans_all_kernel<<<dim3(4, G), dim3(32, 8)>>>(image);

    dim3 grid(NCTA, 3);
    proj_kernel<<<grid, THREADS, SMEM_BYTES>>>(xl, yl, zl, out);
}

// round 16
// speedup vs baseline: 1.0479x; 1.0479x over previous
#include <cuda_runtime.h>
#include <cuda_fp16.h>
#include <cstdint>

#define G     128
#define RSB   132              // padded row stride in BYTES (33 words)
#define GRSB  (G*RSB)          // 16896 bytes per slice
#define NL    200000
#define DX    3.125f
#define CC    0.99658f         // ICC*log2(e)*DX^2
#define KW2C  2.8952918f       // KW2/DX^2
#define TFRAC 0.2016f
#define EOFF  (-0.7016f)       // 0.5 - TFRAC - 1
#define THREADS 512
#define LPT   4
#define LPC   (THREADS*LPT)            // 2048
#define NCTA  ((NL + LPC - 1)/LPC)     // 98 per axis
#define NSTAGE 6

#define SLICE_BYTES  GRSB
#define SMEM_BYTES   (128 + NSTAGE*SLICE_BYTES)   // 101504 -> 2 CTA/SM

// u8 slice-major padded volumes, one per axis
__device__ uint8_t g_tx[G*G*RSB];
__device__ uint8_t g_ty[G*G*RSB];
__device__ uint8_t g_tz[G*G*RSB];

__device__ __forceinline__ uint32_t quant4(float4 v) {
    int b0 = min((int)(v.x * 256.0f), 255);
    int b1 = min((int)(v.y * 256.0f), 255);
    int b2 = min((int)(v.z * 256.0f), 255);
    int b3 = min((int)(v.w * 256.0f), 255);
    return (uint32_t)b0 | ((uint32_t)b1 << 8) | ((uint32_t)b2 << 16) | ((uint32_t)b3 << 24);
}

// Vectorized fused transform (proven). block (32,8), grid (4, G).
__global__ void trans_all_kernel(const float* __restrict__ img) {
    __shared__ uint8_t tzt[G][33];     // [k][j_local], stride 33 -> conflict-free scatter
    const int i  = blockIdx.y;
    const int jb = blockIdx.x * 32;
    const int tx = threadIdx.x;        // k-word index (0..31)
    const int ty = threadIdx.y;
    const int tid = ty * 32 + tx;

    #pragma unroll
    for (int r = 0; r < 4; r++) {
        const int jl = ty + r * 8;
        const int j  = jb + jl;
        const float4 v = *(const float4*)(img + (size_t)(i*G + j)*G + 4*tx);
        const uint32_t w = quant4(v);
        *(uint32_t*)(g_tx + (size_t)(i*G + j)*RSB + 4*tx) = w;
        *(uint32_t*)(g_ty + (size_t)(j*G + i)*RSB + 4*tx) = w;
        tzt[4*tx + 0][jl] = (uint8_t)(w);
        tzt[4*tx + 1][jl] = (uint8_t)(w >> 8);
        tzt[4*tx + 2][jl] = (uint8_t)(w >> 16);
        tzt[4*tx + 3][jl] = (uint8_t)(w >> 24);
    }
    __syncthreads();
    #pragma unroll
    for (int it = 0; it < 4; it++) {
        const int idx = tid + it * 256;        // 1024 words total
        const int k  = idx >> 3;
        const int wj = idx & 7;
        uint32_t w = (uint32_t)tzt[k][4*wj]
                   | ((uint32_t)tzt[k][4*wj + 1] << 8)
                   | ((uint32_t)tzt[k][4*wj + 2] << 16)
                   | ((uint32_t)tzt[k][4*wj + 3] << 24);
        *(uint32_t*)(g_tz + (size_t)(k*G + i)*RSB + jb + 4*wj) = w;
    }
}

// ---------------- TMA / mbarrier helpers (proven) ----------------
__device__ __forceinline__ void mbar_init(uint32_t mbar, uint32_t count) {
    asm volatile("mbarrier.init.shared::cta.b64 [%0], %1;" :: "r"(mbar), "r"(count) : "memory");
}
__device__ __forceinline__ void mbar_expect_tx(uint32_t mbar, uint32_t bytes) {
    asm volatile("mbarrier.arrive.expect_tx.shared::cta.b64 _, [%0], %1;"
                 :: "r"(mbar), "r"(bytes) : "memory");
}
__device__ __forceinline__ void mbar_wait(uint32_t mbar, uint32_t phase) {
    asm volatile(
        "{\n\t"
        ".reg .pred P1;\n\t"
        "LAB_WAIT_%=:\n\t"
        "mbarrier.try_wait.parity.acquire.cta.shared::cta.b64 P1, [%0], %1, 0x989680;\n\t"
        "@P1 bra LAB_DONE_%=;\n\t"
        "bra.uni LAB_WAIT_%=;\n\t"
        "LAB_DONE_%=:\n\t"
        "}"
        :: "r"(mbar), "r"(phase) : "memory");
}
__device__ __forceinline__ void bulk_g2s(uint32_t dst, const void* src, uint32_t bytes, uint32_t mbar) {
    asm volatile("cp.async.bulk.shared::cluster.global.mbarrier::complete_tx::bytes [%0], [%1], %2, [%3];"
                 :: "r"(dst), "l"(src), "r"(bytes), "r"(mbar) : "memory");
}

__global__ __launch_bounds__(THREADS, 2)
void proj_kernel(const float* __restrict__ lx,
                 const float* __restrict__ ly,
                 const float* __restrict__ lz,
                 float* __restrict__ out)
{
    extern __shared__ __align__(128) unsigned char smem_raw[];
    const uint32_t smem_base = (uint32_t)__cvta_generic_to_shared(smem_raw);
    const uint32_t mbar0 = smem_base;            // 6 mbarriers, 8 B apart
    uint8_t* sbuf = (uint8_t*)(smem_raw + 128);

    const int axis = blockIdx.y;
    const int tid  = threadIdx.x;
    const int cta_base = blockIdx.x * LPC;

    const float* lors;
    const uint8_t* vol;
    int q0, q1;
    if (axis == 0)      { lors = lx; vol = g_tx; q0 = 1; q1 = 2; }
    else if (axis == 1) { lors = ly; vol = g_ty; q0 = 0; q1 = 2; }
    else                { lors = lz; vol = g_tz; q0 = 0; q1 = 1; }

    // per-LOR params in CELL units, prefolded by -(TFRAC+1).
    float ua0[LPT], va0[LPT], ddx[LPT], ddy[LPT], total[LPT];
    #pragma unroll
    for (int l = 0; l < LPT; l++) {
        int gi = cta_base + l*THREADS + tid;
        int lr = gi < NL ? gi : NL - 1;
        const float* L6 = lors + lr * 6;
        float px = L6[q0], py = L6[q1];
        ddx[l] = (L6[q0+3] - px) * (1.0f/400.0f);
        ddy[l] = (L6[q1+3] - py) * (1.0f/400.0f);
        ua0[l] = fmaf(px, 0.32f, 64.0f - (TFRAC + 1.0f)) + 0.5f * ddx[l];
        va0[l] = fmaf(py, 0.32f, 64.0f - (TFRAC + 1.0f)) + 0.5f * ddy[l];
        total[l] = 0.0f;
    }

    const __half2 nCC2   = __float2half2_rn(-CC);
    const __half2 KW2C2  = __float2half2_rn(KW2C);
    const __half2 zero2  = __float2half2_rn(0.0f);
    const __half2 B10235 = __float2half2_rn(1023.5f);
    const __half2 C01    = __halves2half2(__float2half(EOFF), __float2half(EOFF + 1.0f));
    const __half2 C22    = __float2half2_rn(2.0f);

    if (tid == 0) {
        #pragma unroll
        for (int s = 0; s < NSTAGE; s++) mbar_init(mbar0 + s*8, 1);
        asm volatile("fence.proxy.async.shared::cta;" ::: "memory");
    }
    __syncthreads();
    if (tid == 0) {
        #pragma unroll
        for (int s = 0; s < NSTAGE; s++) {
            mbar_expect_tx(mbar0 + s*8, SLICE_BYTES);
            bulk_g2s(smem_base + 128 + s*SLICE_BYTES, vol + (size_t)s*GRSB, SLICE_BYTES, mbar0 + s*8);
        }
    }

    // groups of 3 slices; stage group sg alternates 0,3; parity pf flips when sg wraps.
    int sg = 0, pf = 0;
    for (int kp = 0; kp < G; kp += 3) {

        #pragma unroll
        for (int h = 0; h < 3; h++) {
            if (kp + h >= G) break;              // tail group (G % 3 == 2)
            const int s = sg + h;                // <= 5 since sg in {0,3}
            mbar_wait(mbar0 + s*8, pf);
            const uint8_t* slice = sbuf + s * GRSB;
            const float kf = (float)(kp + h);

            #pragma unroll
            for (int l = 0; l < LPT; l++) {
                const float ua = fmaf(kf, ddx[l], ua0[l]);
                const float va = fmaf(kf, ddy[l], va0[l]);

                float af = floorf(ua);
                af = fminf(fmaxf(af, 0.0f), 124.0f);
                float cf = floorf(va);
                cf = fminf(fmaxf(cf, 0.0f), 124.0f);
                const int alo = (int)af;
                const int clo = (int)cf;
                const int d   = clo & 3;
                const int cW  = clo - d;
                const uint32_t selp = 0x3210u + (uint32_t)d * 0x1111u;

                const float eR = af - ua;      // EOFF folded into C01
                const float fR = cf - va;

                // col (f+m)^2 table, m=0..3, fully packed
                __half2 f2  = __hadd2(__float2half2_rn(fR), C01);   // (y0, y1)
                __half2 S0  = __hmul2(f2, f2);
                __half2 f2b = __hadd2(f2, C22);                     // (y2, y3)
                __half2 S1  = __hmul2(f2b, f2b);
                const __half2 P0 = h2exp2(__hmul2(S0, nCC2));
                const __half2 P1 = h2exp2(__hmul2(S1, nCC2));

                // row (e+a)^2 table, a=0..3, fully packed
                __half2 e2  = __hadd2(__float2half2_rn(eR), C01);   // (x0, x1)
                __half2 X01 = __hmul2(e2, e2);
                __half2 e2b = __hadd2(e2, C22);                     // (x2, x3)
                __half2 X23 = __hmul2(e2b, e2b);
                const __half2 W01 = h2exp2(__hmul2(X01, nCC2));
                const __half2 W23 = h2exp2(__hmul2(X23, nCC2));
                const __half2 L01 = __hsub2(KW2C2, X01);
                const __half2 L23 = __hsub2(KW2C2, X23);

                __half2 lb[4], wb[4];
                lb[0] = __low2half2(L01);  lb[1] = __high2half2(L01);
                lb[2] = __low2half2(L23);  lb[3] = __high2half2(L23);
                wb[0] = __low2half2(W01);  wb[1] = __high2half2(W01);
                wb[2] = __low2half2(W23);  wb[3] = __high2half2(W23);

                const uint8_t* rp = slice + alo * RSB + cW;
                __half2 acc2 = zero2;

                #pragma unroll
                for (int a = 0; a < 4; a++) {
                    const uint32_t w0 = *(const uint32_t*)(rp);
                    const uint32_t w1 = *(const uint32_t*)(rp + 4);
                    const uint32_t p  = __byte_perm(w0, w1, selp);
                    const uint32_t e0 = __byte_perm(p, 0x64646464u, 0x4140u);
                    const uint32_t e1 = __byte_perm(p, 0x64646464u, 0x4342u);
                    const __half2 V0 = __hsub2(*(const __half2*)&e0, B10235);
                    const __half2 V1 = __hsub2(*(const __half2*)&e1, B10235);

                    __half2 r2 = __hmul2(__hmul2(__hle2(S0, lb[a]), P0), V0);
                    r2 = __hfma2(__hmul2(__hle2(S1, lb[a]), P1), V1, r2);
                    acc2 = __hfma2(wb[a], r2, acc2);
                    rp += RSB;
                }

                const float2 fr = __half22float2(acc2);
                total[l] += fr.x + fr.y;
            }
        }

        __syncthreads();   // all warps done with stages sg..sg+2
        if (tid == 0) {
            #pragma unroll
            for (int i = 0; i < 3; i++) {
                if (kp + 6 + i < G) {
                    mbar_expect_tx(mbar0 + (sg + i)*8, SLICE_BYTES);
                    bulk_g2s(smem_base + 128 + (sg + i)*SLICE_BYTES,
                             vol + (size_t)(kp + 6 + i)*GRSB, SLICE_BYTES, mbar0 + (sg + i)*8);
                }
            }
        }
        sg += 3; if (sg == NSTAGE) { sg = 0; pf ^= 1; }
    }

    #pragma unroll
    for (int l = 0; l < LPT; l++) {
        int gi = cta_base + l*THREADS + tid;
        if (gi < NL) {
            // path = DX * sqrt(ddx^2 + ddy^2 + 1); u8 decode scale 1/256
            float sfac = sqrtf(fmaf(ddx[l], ddx[l], fmaf(ddy[l], ddy[l], 1.0f)));
            out[axis * NL + gi] = total[l] * (DX / 256.0f) * sfac;
        }
    }
}

extern "C" void kernel_launch(void* const* d_in, const int* in_sizes, int n_in,
                              void* d_out, int out_size)
{
    (void)in_sizes; (void)n_in; (void)out_size;
    const float* image = (const float*)d_in[0];
    const float* xl    = (const float*)d_in[1];
    const float* yl    = (const float*)d_in[2];
    const float* zl    = (const float*)d_in[3];
    float* out = (float*)d_out;

    static bool attr_set = false;
    if (!attr_set) {
        cudaFuncSetAttribute(proj_kernel, cudaFuncAttributeMaxDynamicSharedMemorySize, SMEM_BYTES);
        attr_set = true;
    }

    trans_all_kernel<<<dim3(4, G), dim3(32, 8)>>>(image);

    dim3 grid(NCTA, 3);
    proj_kernel<<<grid, THREADS, SMEM_BYTES>>>(xl, yl, zl, out);
}

// round 17
// speedup vs baseline: 1.0733x; 1.0243x over previous
#include <cuda_runtime.h>
#include <cuda_fp16.h>
#include <cstdint>

#define G     128
#define ROWS  132              // 2 top + 128 + 2 bottom border rows (window max row 131)
#define RSBP  136              // 4 left + 128 + 4 right border bytes (34 words)
#define GRSB  (ROWS*RSBP)      // 17952 bytes per padded slice
#define NL    200000
#define DX    3.125f
#define CC    0.99658f         // ICC*log2(e)*DX^2
#define KW2C  2.8952918f       // KW2/DX^2
#define TFRAC 0.2016f
#define EOFF  (-0.7016f)       // 0.5 - TFRAC - 1
#define THREADS 512
#define LPT   4
#define LPC   (THREADS*LPT)            // 2048
#define NCTA  ((NL + LPC - 1)/LPC)     // 98 per axis
#define NSTAGE 6

#define SLICE_BYTES  GRSB
#define SMEM_BYTES   (128 + NSTAGE*SLICE_BYTES)   // 107840 -> 2 CTA/SM

// u8 slice-major zero-bordered volumes (borders never written -> stay zero
// from static zero-init; transform writes only the interior).
__device__ uint8_t g_tx[G*GRSB];
__device__ uint8_t g_ty[G*GRSB];
__device__ uint8_t g_tz[G*GRSB];

__device__ __forceinline__ uint32_t quant4(float4 v) {
    int b0 = min((int)(v.x * 256.0f), 255);
    int b1 = min((int)(v.y * 256.0f), 255);
    int b2 = min((int)(v.z * 256.0f), 255);
    int b3 = min((int)(v.w * 256.0f), 255);
    return (uint32_t)b0 | ((uint32_t)b1 << 8) | ((uint32_t)b2 << 16) | ((uint32_t)b3 << 24);
}

// interior address: slice s, row r (0..127), col byte c (0..127, word-aligned)
__device__ __forceinline__ size_t vaddr(int s, int r, int c) {
    return (size_t)s * GRSB + (size_t)(r + 2) * RSBP + (c + 4);
}

// Vectorized fused transform. block (32,8), grid (4, G).
__global__ void trans_all_kernel(const float* __restrict__ img) {
    __shared__ uint8_t tzt[G][33];     // [k][j_local]
    const int i  = blockIdx.y;
    const int jb = blockIdx.x * 32;
    const int tx = threadIdx.x;        // k-word index (0..31)
    const int ty = threadIdx.y;
    const int tid = ty * 32 + tx;

    #pragma unroll
    for (int r = 0; r < 4; r++) {
        const int jl = ty + r * 8;
        const int j  = jb + jl;
        const float4 v = *(const float4*)(img + (size_t)(i*G + j)*G + 4*tx);
        const uint32_t w = quant4(v);
        // g_tx: slice=i, row=j, col=k ; g_ty: slice=j, row=i, col=k
        *(uint32_t*)(g_tx + vaddr(i, j, 4*tx)) = w;
        *(uint32_t*)(g_ty + vaddr(j, i, 4*tx)) = w;
        tzt[4*tx + 0][jl] = (uint8_t)(w);
        tzt[4*tx + 1][jl] = (uint8_t)(w >> 8);
        tzt[4*tx + 2][jl] = (uint8_t)(w >> 16);
        tzt[4*tx + 3][jl] = (uint8_t)(w >> 24);
    }
    __syncthreads();
    #pragma unroll
    for (int it = 0; it < 4; it++) {
        const int idx = tid + it * 256;        // 1024 words total
        const int k  = idx >> 3;
        const int wj = idx & 7;
        uint32_t w = (uint32_t)tzt[k][4*wj]
                   | ((uint32_t)tzt[k][4*wj + 1] << 8)
                   | ((uint32_t)tzt[k][4*wj + 2] << 16)
                   | ((uint32_t)tzt[k][4*wj + 3] << 24);
        // g_tz: slice=k, row=i, col=j
        *(uint32_t*)(g_tz + vaddr(k, i, jb + 4*wj)) = w;
    }
}

// ---------------- TMA / mbarrier helpers (proven) ----------------
__device__ __forceinline__ void mbar_init(uint32_t mbar, uint32_t count) {
    asm volatile("mbarrier.init.shared::cta.b64 [%0], %1;" :: "r"(mbar), "r"(count) : "memory");
}
__device__ __forceinline__ void mbar_expect_tx(uint32_t mbar, uint32_t bytes) {
    asm volatile("mbarrier.arrive.expect_tx.shared::cta.b64 _, [%0], %1;"
                 :: "r"(mbar), "r"(bytes) : "memory");
}
__device__ __forceinline__ void mbar_wait(uint32_t mbar, uint32_t phase) {
    asm volatile(
        "{\n\t"
        ".reg .pred P1;\n\t"
        "LAB_WAIT_%=:\n\t"
        "mbarrier.try_wait.parity.acquire.cta.shared::cta.b64 P1, [%0], %1, 0x989680;\n\t"
        "@P1 bra LAB_DONE_%=;\n\t"
        "bra.uni LAB_WAIT_%=;\n\t"
        "LAB_DONE_%=:\n\t"
        "}"
        :: "r"(mbar), "r"(phase) : "memory");
}
__device__ __forceinline__ void bulk_g2s(uint32_t dst, const void* src, uint32_t bytes, uint32_t mbar) {
    asm volatile("cp.async.bulk.shared::cluster.global.mbarrier::complete_tx::bytes [%0], [%1], %2, [%3];"
                 :: "r"(dst), "l"(src), "r"(bytes), "r"(mbar) : "memory");
}

__global__ __launch_bounds__(THREADS, 2)
void proj_kernel(const float* __restrict__ lx,
                 const float* __restrict__ ly,
                 const float* __restrict__ lz,
                 float* __restrict__ out)
{
    extern __shared__ __align__(128) unsigned char smem_raw[];
    const uint32_t smem_base = (uint32_t)__cvta_generic_to_shared(smem_raw);
    const uint32_t mbar0 = smem_base;            // 6 mbarriers, 8 B apart
    uint8_t* sbuf = (uint8_t*)(smem_raw + 128);

    const int axis = blockIdx.y;
    const int tid  = threadIdx.x;
    const int cta_base = blockIdx.x * LPC;

    const float* lors;
    const uint8_t* vol;
    int q0, q1;
    if (axis == 0)      { lors = lx; vol = g_tx; q0 = 1; q1 = 2; }
    else if (axis == 1) { lors = ly; vol = g_ty; q0 = 0; q1 = 2; }
    else                { lors = lz; vol = g_tz; q0 = 0; q1 = 1; }

    // per-LOR params in CELL units, prefolded by -(TFRAC+1).
    // Unclamped anchors are guaranteed in [-2,126]; zero border absorbs them.
    float ua0[LPT], va0[LPT], ddx[LPT], ddy[LPT], total[LPT];
    #pragma unroll
    for (int l = 0; l < LPT; l++) {
        int gi = cta_base + l*THREADS + tid;
        int lr = gi < NL ? gi : NL - 1;
        const float* L6 = lors + lr * 6;
        float px = L6[q0], py = L6[q1];
        ddx[l] = (L6[q0+3] - px) * (1.0f/400.0f);
        ddy[l] = (L6[q1+3] - py) * (1.0f/400.0f);
        ua0[l] = fmaf(px, 0.32f, 64.0f - (TFRAC + 1.0f)) + 0.5f * ddx[l];
        va0[l] = fmaf(py, 0.32f, 64.0f - (TFRAC + 1.0f)) + 0.5f * ddy[l];
        total[l] = 0.0f;
    }

    const __half2 nCC2   = __float2half2_rn(-CC);
    const __half2 KW2C2  = __float2half2_rn(KW2C);
    const __half2 zero2  = __float2half2_rn(0.0f);
    const __half2 B10235 = __float2half2_rn(1023.5f);
    const __half2 C01    = __halves2half2(__float2half(EOFF), __float2half(EOFF + 1.0f));
    const __half2 C22    = __float2half2_rn(2.0f);

    if (tid == 0) {
        #pragma unroll
        for (int s = 0; s < NSTAGE; s++) mbar_init(mbar0 + s*8, 1);
        asm volatile("fence.proxy.async.shared::cta;" ::: "memory");
    }
    __syncthreads();
    if (tid == 0) {
        #pragma unroll
        for (int s = 0; s < NSTAGE; s++) {
            mbar_expect_tx(mbar0 + s*8, SLICE_BYTES);
            bulk_g2s(smem_base + 128 + s*SLICE_BYTES, vol + (size_t)s*GRSB, SLICE_BYTES, mbar0 + s*8);
        }
    }

    // groups of 3 slices; stage group sg alternates 0,3; parity pf flips on wrap.
    int sg = 0, pf = 0;
    for (int kp = 0; kp < G; kp += 3) {

        #pragma unroll
        for (int h = 0; h < 3; h++) {
            if (kp + h >= G) break;              // tail group (G % 3 == 2)
            const int s = sg + h;
            mbar_wait(mbar0 + s*8, pf);
            // fold border offset: +2 rows, +4 cols
            const uint8_t* slice = sbuf + s * GRSB + 2*RSBP + 4;
            const float kf = (float)(kp + h);

            #pragma unroll
            for (int l = 0; l < LPT; l++) {
                const float ua = fmaf(kf, ddx[l], ua0[l]);
                const float va = fmaf(kf, ddy[l], va0[l]);

                const float af = floorf(ua);      // in [-2, 126], no clamp needed
                const float cf = floorf(va);
                const int alo = (int)af;
                const int clo = (int)cf;
                const int d   = clo & 3;          // correct for negative clo
                const int cW  = clo - d;
                const uint32_t selp = 0x3210u + (uint32_t)d * 0x1111u;

                const float eR = af - ua;      // EOFF folded into C01
                const float fR = cf - va;

                // col (f+m)^2 table, m=0..3, fully packed
                __half2 f2  = __hadd2(__float2half2_rn(fR), C01);   // (y0, y1)
                __half2 S0  = __hmul2(f2, f2);
                __half2 f2b = __hadd2(f2, C22);                     // (y2, y3)
                __half2 S1  = __hmul2(f2b, f2b);
                const __half2 P0 = h2exp2(__hmul2(S0, nCC2));
                const __half2 P1 = h2exp2(__hmul2(S1, nCC2));

                // row (e+a)^2 table, a=0..3, fully packed
                __half2 e2  = __hadd2(__float2half2_rn(eR), C01);   // (x0, x1)
                __half2 X01 = __hmul2(e2, e2);
                __half2 e2b = __hadd2(e2, C22);                     // (x2, x3)
                __half2 X23 = __hmul2(e2b, e2b);
                const __half2 W01 = h2exp2(__hmul2(X01, nCC2));
                const __half2 W23 = h2exp2(__hmul2(X23, nCC2));
                const __half2 L01 = __hsub2(KW2C2, X01);
                const __half2 L23 = __hsub2(KW2C2, X23);

                __half2 lb[4], wb[4];
                lb[0] = __low2half2(L01);  lb[1] = __high2half2(L01);
                lb[2] = __low2half2(L23);  lb[3] = __high2half2(L23);
                wb[0] = __low2half2(W01);  wb[1] = __high2half2(W01);
                wb[2] = __low2half2(W23);  wb[3] = __high2half2(W23);

                const uint8_t* rp = slice + alo * RSBP + cW;
                __half2 acc2 = zero2;

                #pragma unroll
                for (int a = 0; a < 4; a++) {
                    const uint32_t w0 = *(const uint32_t*)(rp);
                    const uint32_t w1 = *(const uint32_t*)(rp + 4);
                    const uint32_t p  = __byte_perm(w0, w1, selp);
                    const uint32_t e0 = __byte_perm(p, 0x64646464u, 0x4140u);
                    const uint32_t e1 = __byte_perm(p, 0x64646464u, 0x4342u);
                    const __half2 V0 = __hsub2(*(const __half2*)&e0, B10235);
                    const __half2 V1 = __hsub2(*(const __half2*)&e1, B10235);

                    __half2 r2 = __hmul2(__hmul2(__hle2(S0, lb[a]), P0), V0);
                    r2 = __hfma2(__hmul2(__hle2(S1, lb[a]), P1), V1, r2);
                    acc2 = __hfma2(wb[a], r2, acc2);
                    rp += RSBP;
                }

                const float2 fr = __half22float2(acc2);
                total[l] += fr.x + fr.y;
            }
        }

        __syncthreads();   // all warps done with stages sg..sg+2
        if (tid == 0) {
            #pragma unroll
            for (int i = 0; i < 3; i++) {
                if (kp + 6 + i < G) {
                    mbar_expect_tx(mbar0 + (sg + i)*8, SLICE_BYTES);
                    bulk_g2s(smem_base + 128 + (sg + i)*SLICE_BYTES,
                             vol + (size_t)(kp + 6 + i)*GRSB, SLICE_BYTES, mbar0 + (sg + i)*8);
                }
            }
        }
        sg += 3; if (sg == NSTAGE) { sg = 0; pf ^= 1; }
    }

    #pragma unroll
    for (int l = 0; l < LPT; l++) {
        int gi = cta_base + l*THREADS + tid;
        if (gi < NL) {
            // path = DX * sqrt(ddx^2 + ddy^2 + 1); u8 decode scale 1/256
            float sfac = sqrtf(fmaf(ddx[l], ddx[l], fmaf(ddy[l], ddy[l], 1.0f)));
            out[axis * NL + gi] = total[l] * (DX / 256.0f) * sfac;
        }
    }
}

extern "C" void kernel_launch(void* const* d_in, const int* in_sizes, int n_in,
                              void* d_out, int out_size)
{
    (void)in_sizes; (void)n_in; (void)out_size;
    const float* image = (const float*)d_in[0];
    const float* xl    = (const float*)d_in[1];
    const float* yl    = (const float*)d_in[2];
    const float* zl    = (const float*)d_in[3];
    float* out = (float*)d_out;

    static bool attr_set = false;
    if (!attr_set) {
        cudaFuncSetAttribute(proj_kernel, cudaFuncAttributeMaxDynamicSharedMemorySize, SMEM_BYTES);
        attr_set = true;
    }

    trans_all_kernel<<<dim3(4, G), dim3(32, 8)>>>(image);

    dim3 grid(NCTA, 3);
    proj_kernel<<<grid, THREADS, SMEM_BYTES>>>(xl, yl, zl, out);
}